// round 7
// baseline (speedup 1.0000x reference)
#include <cuda_runtime.h>
#include <cuda_bf16.h>

// GRU scan: B=2048 sequences, T=2048 steps, D=3 input, H=32 hidden.
// out[b, t] = h[0] after step t.
//
// R7: R6 structure (two batches per warp packed as f32x2, Whh duplicated
// into both halves of 96 u64 regs, smem double-buffered h exchange with one
// syncwarp/step) + activation slimming: hardware tanh.approx.f32 for tanh
// AND sigmoid (0.5*tanh(x/2)+0.5), removing the expf/fdividef chains.
// Matvec is fma-pipe bound (fma2 effective rt~3 from RF banking); everything
// else is overhead to be minimized.

#define T_DIM 2048
#define B_DIM 2048

typedef unsigned long long u64;

__device__ __forceinline__ u64 fma2(u64 a, u64 b, u64 c) {
    u64 d;
    asm("fma.rn.f32x2 %0, %1, %2, %3;" : "=l"(d) : "l"(a), "l"(b), "l"(c));
    return d;
}

__device__ __forceinline__ u64 pack2(float a, float b) {
    u64 d;
    asm("mov.b64 %0, {%1, %2};" : "=l"(d) : "f"(a), "f"(b));
    return d;
}

__device__ __forceinline__ void unpack2(u64 p, float& a, float& b) {
    asm("mov.b64 {%0, %1}, %2;" : "=f"(a), "=f"(b) : "l"(p));
}

__device__ __forceinline__ float tanh_fast(float x) {
    float y;
    asm("tanh.approx.f32 %0, %1;" : "=f"(y) : "f"(x));
    return y;
}

// sigmoid(x) = 0.5*tanh(0.5x) + 0.5
__device__ __forceinline__ float sigm_fast(float x) {
    return fmaf(0.5f, tanh_fast(0.5f * x), 0.5f);
}

__global__ void __launch_bounds__(128, 2)
gru_scan_kernel(const float* __restrict__ inp,      // [B, T, 3]
                const float* __restrict__ wih,      // [96, 3]
                const float* __restrict__ whh,      // [96, 32]
                const float* __restrict__ bias,     // [96]
                const float* __restrict__ bias_n,   // [32]
                float* __restrict__ out)            // [B, T]
{
    const int lane = threadIdx.x & 31;
    const int warp = threadIdx.x >> 5;
    const int bp   = blockIdx.x * 4 + warp;     // batch-pair index (0..1023)
    const int b0   = 2 * bp;                    // handles batches b0, b0+1

    // per-warp double-buffered packed-h slab; 16B-aligned for LDS.128
    __shared__ __align__(16) u64 hbuf[4][2][32];

    // --- Whh rows for this lane, duplicated into both f32x2 halves ---
    u64 wr[32], wz[32], wa[32];
#pragma unroll
    for (int k = 0; k < 32; ++k) {
        float r = whh[(      lane) * 32 + k];
        float z = whh[(32 +  lane) * 32 + k];
        float a = whh[(64 +  lane) * 32 + k];
        wr[k] = pack2(r, r);
        wz[k] = pack2(z, z);
        wa[k] = pack2(a, a);
    }
    const float wir0 = wih[lane * 3 + 0], wir1 = wih[lane * 3 + 1], wir2 = wih[lane * 3 + 2];
    const float wiz0 = wih[(32 + lane) * 3 + 0], wiz1 = wih[(32 + lane) * 3 + 1], wiz2 = wih[(32 + lane) * 3 + 2];
    const float wia0 = wih[(64 + lane) * 3 + 0], wia1 = wih[(64 + lane) * 3 + 1], wia2 = wih[(64 + lane) * 3 + 2];
    const float bir = bias[lane], biz = bias[32 + lane];
    const float bia = bias[64 + lane] + bias_n[lane];   // bias_n folded into a-gate

    const float* xp = inp + (size_t)b0 * T_DIM * 3;
    float*       op = out + (size_t)b0 * T_DIM;

    float ha = 0.0f, hb = 0.0f;   // hidden unit `lane` of batch b0 / b0+1
    float xa0 = __ldg(xp + 0),             xa1 = __ldg(xp + 1),             xa2 = __ldg(xp + 2);
    float xb0 = __ldg(xp + T_DIM * 3 + 0), xb1 = __ldg(xp + T_DIM * 3 + 1), xb2 = __ldg(xp + T_DIM * 3 + 2);

    for (int t = 0; t < T_DIM; ++t) {
        // scalar input gates for both batches (shared weight regs)
        float ira = fmaf(wir2, xa2, fmaf(wir1, xa1, fmaf(wir0, xa0, bir)));
        float iza = fmaf(wiz2, xa2, fmaf(wiz1, xa1, fmaf(wiz0, xa0, biz)));
        float iaa = fmaf(wia2, xa2, fmaf(wia1, xa1, fmaf(wia0, xa0, bia)));
        float irb = fmaf(wir2, xb2, fmaf(wir1, xb1, fmaf(wir0, xb0, bir)));
        float izb = fmaf(wiz2, xb2, fmaf(wiz1, xb1, fmaf(wiz0, xb0, biz)));
        float iab = fmaf(wia2, xb2, fmaf(wia1, xb1, fmaf(wia0, xb0, bia)));
        {   // prefetch next step's x for both batches (clamped, branch-free)
            int tn = (t + 1 < T_DIM) ? (t + 1) : t;
            const float* nx = xp + (size_t)tn * 3;
            xa0 = __ldg(nx + 0);             xa1 = __ldg(nx + 1);             xa2 = __ldg(nx + 2);
            xb0 = __ldg(nx + T_DIM * 3 + 0); xb1 = __ldg(nx + T_DIM * 3 + 1); xb2 = __ldg(nx + T_DIM * 3 + 2);
        }

        // publish packed h, broadcast-read all 32 packed h values.
        // Double-buffered slot: data dependence guarantees slot t&1 is fully
        // read before being rewritten at t+2 -> one syncwarp per step.
        const int slot = t & 1;
        hbuf[warp][slot][lane] = pack2(ha, hb);
        __syncwarp();

        u64 ar = 0ull, az = 0ull, aa = 0ull;
        const ulonglong2* hp =
            reinterpret_cast<const ulonglong2*>(&hbuf[warp][slot][0]);
#pragma unroll
        for (int i = 0; i < 16; ++i) {
            ulonglong2 v = hp[i];               // h2[2i], h2[2i+1] (broadcast)
            // 3 consecutive ops share v.x (then v.y): reuse-cache friendly
            ar = fma2(wr[2 * i],     v.x, ar);
            az = fma2(wz[2 * i],     v.x, az);
            aa = fma2(wa[2 * i],     v.x, aa);
            ar = fma2(wr[2 * i + 1], v.y, ar);
            az = fma2(wz[2 * i + 1], v.y, az);
            aa = fma2(wa[2 * i + 1], v.y, aa);
        }
        float hra, hrb, hza, hzb, haa, hab;
        unpack2(ar, hra, hrb);
        unpack2(az, hza, hzb);
        unpack2(aa, haa, hab);

        // slim activations: HW tanh.approx for sigmoid and tanh
        float ra = sigm_fast(ira + hra);
        float za = sigm_fast(iza + hza);
        float na = tanh_fast(fmaf(ra, haa, iaa));
        ha = fmaf(za, ha - na, na);

        float rb = sigm_fast(irb + hrb);
        float zb = sigm_fast(izb + hzb);
        float nb = tanh_fast(fmaf(rb, hab, iab));
        hb = fmaf(zb, hb - nb, nb);

        if (lane == 0) {
            op[t]         = ha;
            op[T_DIM + t] = hb;
        }
    }
}

extern "C" void kernel_launch(void* const* d_in, const int* in_sizes, int n_in,
                              void* d_out, int out_size) {
    const float* inp    = (const float*)d_in[0];
    const float* wih    = (const float*)d_in[1];
    const float* whh    = (const float*)d_in[2];
    const float* bias   = (const float*)d_in[3];
    const float* bias_n = (const float*)d_in[4];
    float* out = (float*)d_out;

    // 2 batches per warp, 4 warps per CTA -> 256 CTAs, 1024 warps.
    gru_scan_kernel<<<B_DIM / 8, 128>>>(inp, wih, whh, bias, bias_n, out);
}

// round 8
// speedup vs baseline: 1.4545x; 1.4545x over previous
#include <cuda_runtime.h>
#include <cuda_bf16.h>

// GRU scan: B=2048 sequences, T=2048 steps, D=3 input, H=32 hidden.
// out[b, t] = h[0] after step t.
//
// R8 = R6 (known-good 855us) + accumulator chain split.
//  - two batches per warp packed as f32x2; Whh duplicated into both halves
//    of 96 u64 regs; smem double-buffered h exchange, one syncwarp/step.
//  - activations via EX2/RCP (expf) — tanh.approx REGRESSED on sm_103a
//    (expanded to fma-pipe polynomial, +50% fma work; quickref MUFU list
//    has no TANH).
//  - NEW: each gate accumulator split into two independent chains
//    (k in [0,16) and [16,32)), halving the serial fma2 dependency depth
//    from ~128 to ~64 cycles; folded with add.rn.f32x2 at the end.

#define T_DIM 2048
#define B_DIM 2048

typedef unsigned long long u64;

__device__ __forceinline__ u64 fma2(u64 a, u64 b, u64 c) {
    u64 d;
    asm("fma.rn.f32x2 %0, %1, %2, %3;" : "=l"(d) : "l"(a), "l"(b), "l"(c));
    return d;
}

__device__ __forceinline__ u64 add2(u64 a, u64 b) {
    u64 d;
    asm("add.rn.f32x2 %0, %1, %2;" : "=l"(d) : "l"(a), "l"(b));
    return d;
}

__device__ __forceinline__ u64 pack2(float a, float b) {
    u64 d;
    asm("mov.b64 %0, {%1, %2};" : "=l"(d) : "f"(a), "f"(b));
    return d;
}

__device__ __forceinline__ void unpack2(u64 p, float& a, float& b) {
    asm("mov.b64 {%0, %1}, %2;" : "=f"(a), "=f"(b) : "l"(p));
}

__device__ __forceinline__ float sigm_f(float x) {
    return __fdividef(1.0f, 1.0f + __expf(-x));
}

__device__ __forceinline__ float tanh_f(float x) {
    return 1.0f - __fdividef(2.0f, __expf(2.0f * x) + 1.0f);
}

__global__ void __launch_bounds__(128, 2)
gru_scan_kernel(const float* __restrict__ inp,      // [B, T, 3]
                const float* __restrict__ wih,      // [96, 3]
                const float* __restrict__ whh,      // [96, 32]
                const float* __restrict__ bias,     // [96]
                const float* __restrict__ bias_n,   // [32]
                float* __restrict__ out)            // [B, T]
{
    const int lane = threadIdx.x & 31;
    const int warp = threadIdx.x >> 5;
    const int bp   = blockIdx.x * 4 + warp;     // batch-pair index (0..1023)
    const int b0   = 2 * bp;                    // handles batches b0, b0+1

    // per-warp double-buffered packed-h slab; 16B-aligned for LDS.128
    __shared__ __align__(16) u64 hbuf[4][2][32];

    // --- Whh rows for this lane, duplicated into both f32x2 halves ---
    u64 wr[32], wz[32], wa[32];
#pragma unroll
    for (int k = 0; k < 32; ++k) {
        float r = whh[(      lane) * 32 + k];
        float z = whh[(32 +  lane) * 32 + k];
        float a = whh[(64 +  lane) * 32 + k];
        wr[k] = pack2(r, r);
        wz[k] = pack2(z, z);
        wa[k] = pack2(a, a);
    }
    const float wir0 = wih[lane * 3 + 0], wir1 = wih[lane * 3 + 1], wir2 = wih[lane * 3 + 2];
    const float wiz0 = wih[(32 + lane) * 3 + 0], wiz1 = wih[(32 + lane) * 3 + 1], wiz2 = wih[(32 + lane) * 3 + 2];
    const float wia0 = wih[(64 + lane) * 3 + 0], wia1 = wih[(64 + lane) * 3 + 1], wia2 = wih[(64 + lane) * 3 + 2];
    const float bir = bias[lane], biz = bias[32 + lane];
    const float bia = bias[64 + lane] + bias_n[lane];   // bias_n folded into a-gate

    const float* xp = inp + (size_t)b0 * T_DIM * 3;
    float*       op = out + (size_t)b0 * T_DIM;

    float ha = 0.0f, hb = 0.0f;   // hidden unit `lane` of batch b0 / b0+1
    float xa0 = __ldg(xp + 0),             xa1 = __ldg(xp + 1),             xa2 = __ldg(xp + 2);
    float xb0 = __ldg(xp + T_DIM * 3 + 0), xb1 = __ldg(xp + T_DIM * 3 + 1), xb2 = __ldg(xp + T_DIM * 3 + 2);

    for (int t = 0; t < T_DIM; ++t) {
        // scalar input gates for both batches (shared weight regs)
        float ira = fmaf(wir2, xa2, fmaf(wir1, xa1, fmaf(wir0, xa0, bir)));
        float iza = fmaf(wiz2, xa2, fmaf(wiz1, xa1, fmaf(wiz0, xa0, biz)));
        float iaa = fmaf(wia2, xa2, fmaf(wia1, xa1, fmaf(wia0, xa0, bia)));
        float irb = fmaf(wir2, xb2, fmaf(wir1, xb1, fmaf(wir0, xb0, bir)));
        float izb = fmaf(wiz2, xb2, fmaf(wiz1, xb1, fmaf(wiz0, xb0, biz)));
        float iab = fmaf(wia2, xb2, fmaf(wia1, xb1, fmaf(wia0, xb0, bia)));
        {   // prefetch next step's x for both batches (clamped, branch-free)
            int tn = (t + 1 < T_DIM) ? (t + 1) : t;
            const float* nx = xp + (size_t)tn * 3;
            xa0 = __ldg(nx + 0);             xa1 = __ldg(nx + 1);             xa2 = __ldg(nx + 2);
            xb0 = __ldg(nx + T_DIM * 3 + 0); xb1 = __ldg(nx + T_DIM * 3 + 1); xb2 = __ldg(nx + T_DIM * 3 + 2);
        }

        // publish packed h, broadcast-read all 32 packed h values.
        // Double-buffered slot: data dependence guarantees slot t&1 is fully
        // read before being rewritten at t+2 -> one syncwarp per step.
        const int slot = t & 1;
        hbuf[warp][slot][lane] = pack2(ha, hb);
        __syncwarp();

        // matvec with SPLIT accumulators: two independent chains per gate
        // (k-halves [0,16) and [16,32)), halving serial dependency depth.
        u64 ar0 = 0ull, az0 = 0ull, aa0 = 0ull;
        u64 ar1 = 0ull, az1 = 0ull, aa1 = 0ull;
        const ulonglong2* hp =
            reinterpret_cast<const ulonglong2*>(&hbuf[warp][slot][0]);
#pragma unroll
        for (int i = 0; i < 8; ++i) {
            ulonglong2 v0 = hp[i];          // h2[2i],    h2[2i+1]
            ulonglong2 v1 = hp[i + 8];      // h2[2i+16], h2[2i+17]
            ar0 = fma2(wr[2 * i],          v0.x, ar0);
            ar1 = fma2(wr[2 * i + 16],     v1.x, ar1);
            az0 = fma2(wz[2 * i],          v0.x, az0);
            az1 = fma2(wz[2 * i + 16],     v1.x, az1);
            aa0 = fma2(wa[2 * i],          v0.x, aa0);
            aa1 = fma2(wa[2 * i + 16],     v1.x, aa1);
            ar0 = fma2(wr[2 * i + 1],      v0.y, ar0);
            ar1 = fma2(wr[2 * i + 17],     v1.y, ar1);
            az0 = fma2(wz[2 * i + 1],      v0.y, az0);
            az1 = fma2(wz[2 * i + 17],     v1.y, az1);
            aa0 = fma2(wa[2 * i + 1],      v0.y, aa0);
            aa1 = fma2(wa[2 * i + 17],     v1.y, aa1);
        }
        u64 ar = add2(ar0, ar1);
        u64 az = add2(az0, az1);
        u64 aa = add2(aa0, aa1);

        float hra, hrb, hza, hzb, haa, hab;
        unpack2(ar, hra, hrb);
        unpack2(az, hza, hzb);
        unpack2(aa, haa, hab);

        // EX2/RCP activations (proven path)
        float ra = sigm_f(ira + hra);
        float za = sigm_f(iza + hza);
        float na = tanh_f(fmaf(ra, haa, iaa));
        ha = fmaf(za, ha - na, na);

        float rb = sigm_f(irb + hrb);
        float zb = sigm_f(izb + hzb);
        float nb = tanh_f(fmaf(rb, hab, iab));
        hb = fmaf(zb, hb - nb, nb);

        if (lane == 0) {
            op[t]         = ha;
            op[T_DIM + t] = hb;
        }
    }
}

extern "C" void kernel_launch(void* const* d_in, const int* in_sizes, int n_in,
                              void* d_out, int out_size) {
    const float* inp    = (const float*)d_in[0];
    const float* wih    = (const float*)d_in[1];
    const float* whh    = (const float*)d_in[2];
    const float* bias   = (const float*)d_in[3];
    const float* bias_n = (const float*)d_in[4];
    float* out = (float*)d_out;

    // 2 batches per warp, 4 warps per CTA -> 256 CTAs, 1024 warps.
    gru_scan_kernel<<<B_DIM / 8, 128>>>(inp, wih, whh, bias, bias_n, out);
}